// round 9
// baseline (speedup 1.0000x reference)
#include <cuda_runtime.h>
#include <math.h>

// Problem constants
#define Bsz    64
#define Ssz    512
#define Hsz    256
#define Dsz    207
#define DINsz  414

// Partition: 4 batch-groups x 32 hidden-groups = 128 blocks
// Each block: 16 batches as TWO pipelined streams of 8, 8 hidden units.
#define GRID    128
#define THREADS 512
#define NB      16
#define NBH     8         // batches per stream
#define NI      8         // hidden units per block
#define NROWB   24        // 3*NI gate rows
#define XS_STR  420       // 414 padded; 420 % 32 == 4 -> conflict-free
#define HS_STR  260       // 256 padded; 260 % 32 == 4

// Persistent global state (device globals: no runtime allocation)
__device__ float    g_h[Bsz * Hsz];
__device__ float    g_xh[Bsz * Dsz];
__device__ unsigned g_flags[GRID * 16];   // two flags per block (one per stream)

__device__ __forceinline__ void bar_release(int s, unsigned target) {
    __syncthreads();
    if (threadIdx.x == 0) {
        asm volatile("st.release.gpu.u32 [%0], %1;"
                     :: "l"(g_flags + blockIdx.x * 16 + s * 8), "r"(target) : "memory");
    }
}
__device__ __forceinline__ void bar_wait(int gbase, int s, unsigned target) {
    if (threadIdx.x < 32) {
        const unsigned* p = g_flags + (gbase + threadIdx.x) * 16 + s * 8;
        unsigned v;
        do {
            asm volatile("ld.acquire.gpu.u32 %0, [%1];" : "=r"(v) : "l"(p) : "memory");
        } while ((int)(v - target) < 0);
    }
    __syncthreads();
}

__device__ __forceinline__ void fma4(float& a, const float4 wgt, const float4 xv) {
    a = fmaf(wgt.x, xv.x, a);
    a = fmaf(wgt.y, xv.y, a);
    a = fmaf(wgt.z, xv.z, a);
    a = fmaf(wgt.w, xv.w, a);
}
__device__ __forceinline__ float redq(float a) {   // sum over 4 K-quarters
    a += __shfl_xor_sync(0xffffffffu, a, 8);
    a += __shfl_xor_sync(0xffffffffu, a, 16);
    return a;
}

__global__ void __launch_bounds__(THREADS, 1)
rnn_imputer_kernel(const float* __restrict__ x, const float* __restrict__ mask,
                   const float* __restrict__ Wih, const float* __restrict__ Whh,
                   const float* __restrict__ bih, const float* __restrict__ bhh,
                   const float* __restrict__ Wro, const float* __restrict__ bro,
                   float* __restrict__ out)
{
    extern __shared__ float sm[];
    float* wih_s = sm;                        // 24*420
    float* wa_s  = wih_s + NROWB * XS_STR;    // 31*260 (Whh rows 0..23, Wro 24..)
    float* xs    = wa_s + 31 * HS_STR;        // 2 * 8*420  [x_p | mask] per stream
    float* hs    = xs + 2 * NBH * XS_STR;     // 2 * 8*260
    float* gi_s  = hs + 2 * NBH * HS_STR;     // 2 * 8*24
    float* gh_s  = gi_s + 2 * NBH * NROWB;    // 2 * 8*24
    float* bih_s = gh_s + 2 * NBH * NROWB;    // 24
    float* bhh_s = bih_s + NROWB;             // 24
    float* bro_s = bhh_s + NROWB;             // 8

    const int tid = threadIdx.x, blk = blockIdx.x;
    const int bg = blk >> 5, ig = blk & 31;
    const int gbase = bg << 5;
    const int b0 = bg * NB;
    const int i0 = ig * NI;
    const int d0 = ig * 6 + (ig < 15 ? ig : 15);
    const int nd = (ig < 15) ? 7 : 6;

    const int lane = tid & 31, warp = tid >> 5;
    const int lb = lane & 7;                 // batch within stream (0..7)
    const int kq = lane >> 3;                // K quarter (0..3)

    // ---- one-time staging ----
    for (int idx = tid; idx < NROWB * DINsz; idx += THREADS) {
        int r = idx / DINsz, k = idx - r * DINsz;
        int ii = r / 3, g = r - ii * 3;
        wih_s[r * XS_STR + k] = Wih[(g * Hsz + i0 + ii) * DINsz + k];
    }
    for (int idx = tid; idx < NROWB * (XS_STR - DINsz); idx += THREADS) {
        int r = idx / 6, c = idx - r * 6;
        wih_s[r * XS_STR + DINsz + c] = 0.f;
    }
    for (int idx = tid; idx < NROWB * Hsz; idx += THREADS) {
        int r = idx >> 8, k = idx & 255;
        int ii = r / 3, g = r - ii * 3;
        wa_s[r * HS_STR + k] = Whh[(g * Hsz + i0 + ii) * Hsz + k];
    }
    for (int idx = tid; idx < nd * Hsz; idx += THREADS) {
        int r = idx >> 8, k = idx & 255;
        wa_s[(NROWB + r) * HS_STR + k] = Wro[(d0 + r) * Hsz + k];
    }
    if (tid < 2 * NBH * 2)   // zero xs[*][414..415] both streams
        xs[(tid >> 1) * XS_STR + DINsz + (tid & 1)] = 0.f;
    if (tid < NROWB) {
        int ii = tid / 3, g = tid - ii * 3;
        bih_s[tid] = bih[g * Hsz + i0 + ii];
        bhh_s[tid] = bhh[g * Hsz + i0 + ii];
    }
    if (tid < nd) bro_s[tid] = bro[d0 + tid];

    // prefetch x[0], mask[0] for both streams (xs is [stream*8 + b] contiguous = 16 batches)
    for (int idx = tid; idx < NB * Dsz; idx += THREADS) {
        int bb = idx / Dsz, k = idx - bb * Dsz;
        size_t o = ((size_t)(b0 + bb) * Ssz) * Dsz + k;
        xs[bb * XS_STR + k] = x[o];
        xs[bb * XS_STR + Dsz + k] = mask[o];
    }
    // zero my slice of h state (all 16 batches)
    if (tid < NB * NI) {
        int bb = tid >> 3, ii = tid & 7;
        g_h[(b0 + bb) * Hsz + i0 + ii] = 0.f;
    }

    unsigned tgt[2];
    tgt[0] = *(volatile unsigned*)(g_flags + blk * 16);
    tgt[1] = *(volatile unsigned*)(g_flags + blk * 16 + 8);
    bar_release(0, ++tgt[0]);
    bar_release(1, ++tgt[1]);
    // top-of-loop waits consume these targets

    for (int t = 0; t < Ssz; ++t) {
        // ================= A phase, per stream =================
        for (int s = 0; s < 2; ++s) {
            const int sb = s * NBH;                 // stream batch base (0 or 8)
            float* hss = hs + sb * HS_STR;
            float* ghs = gh_s + sb * NROWB;

            bar_wait(gbase, s, tgt[s]);             // h_t(stream s) ready

            // stage h_t for this stream (8 batches x 64 float4 = 512 loads)
            {
                int bb = tid >> 6, c = tid & 63;
                float4 v = __ldcg(reinterpret_cast<const float4*>(g_h + (b0 + sb + bb) * Hsz) + c);
                *(reinterpret_cast<float4*>(hss + bb * HS_STR) + c) = v;
            }
            __syncthreads();

            const float4* xp = reinterpret_cast<const float4*>(hss + lb * HS_STR) + kq * 16;

            // A1a: warps 0-7 gate rows 0-7; warps 8-14 readout rows
            if (warp < 8) {
                const int r = warp;
                float a = 0.f;
                const float4* wp = reinterpret_cast<const float4*>(wa_s + r * HS_STR) + kq * 16;
#pragma unroll
                for (int kk = 0; kk < 16; ++kk) fma4(a, wp[kk], xp[kk]);
                a = redq(a);
                if (lane < 8) ghs[lb * NROWB + r] = a;
            } else if (warp - 8 < nd) {
                const int dd = warp - 8;
                float a = 0.f;
                const float4* wp = reinterpret_cast<const float4*>(wa_s + (NROWB + dd) * HS_STR) + kq * 16;
#pragma unroll
                for (int kk = 0; kk < 16; ++kk) fma4(a, wp[kk], xp[kk]);
                a = redq(a);
                if (lane < 8) {
                    int gb = b0 + sb + lb;
                    float v = a + bro_s[dd];
                    g_xh[gb * Dsz + d0 + dd] = v;
                    out[((size_t)gb * Ssz + t) * Dsz + d0 + dd] = v;
                }
            }
            if (t < Ssz - 1) {
                bar_release(s, ++tgt[s]);           // publish x_hat (syncthreads inside)

                // A2: remaining gate rows 8-23 (2 per warp)
                {
                    const int r = 8 + warp;         // rows 8..23
                    float a = 0.f;
                    const float4* wp = reinterpret_cast<const float4*>(wa_s + r * HS_STR) + kq * 16;
#pragma unroll
                    for (int kk = 0; kk < 16; ++kk) fma4(a, wp[kk], xp[kk]);
                    a = redq(a);
                    if (lane < 8) ghs[lb * NROWB + r] = a;
                }
            }
        }
        if (t == Ssz - 1) break;

        // ================= B phase, per stream =================
        for (int s = 0; s < 2; ++s) {
            const int sb = s * NBH;
            float* xss = xs + sb * XS_STR;
            float* hss = hs + sb * HS_STR;
            float* gis = gi_s + sb * NROWB;
            float* ghs = gh_s + sb * NROWB;

            bar_wait(gbase, s, tgt[s]);             // peers' x_hat ready

            // patch unobserved entries with x_hat
            for (int idx = tid; idx < NBH * Dsz; idx += THREADS) {
                int bb = idx / Dsz, k = idx - bb * Dsz;
                float mv = xss[bb * XS_STR + Dsz + k];
                if (mv <= 0.5f)
                    xss[bb * XS_STR + k] = __ldcg(g_xh + (b0 + sb + bb) * Dsz + k);
            }
            __syncthreads();

            // gi = Wih_slice @ x_in : rows {w, w+16(if w<8)}, K quarters of 104
            {
                const float4* xp = reinterpret_cast<const float4*>(xss + lb * XS_STR) + kq * 26;
                const int r1 = warp;
                float a1 = 0.f;
                const float4* w1 = reinterpret_cast<const float4*>(wih_s + r1 * XS_STR) + kq * 26;
                if (warp < 8) {
                    const int r2 = warp + 16;
                    float a2 = 0.f;
                    const float4* w2 = reinterpret_cast<const float4*>(wih_s + r2 * XS_STR) + kq * 26;
#pragma unroll
                    for (int kk = 0; kk < 26; ++kk) {
                        float4 xv = xp[kk];
                        fma4(a1, w1[kk], xv);
                        fma4(a2, w2[kk], xv);
                    }
                    a1 = redq(a1); a2 = redq(a2);
                    if (lane < 8) {
                        gis[lb * NROWB + r1] = a1;
                        gis[lb * NROWB + r2] = a2;
                    }
                } else {
#pragma unroll
                    for (int kk = 0; kk < 26; ++kk) fma4(a1, w1[kk], xp[kk]);
                    a1 = redq(a1);
                    if (lane < 8) gis[lb * NROWB + r1] = a1;
                }
            }
            __syncthreads();

            // gates -> h_new (8 batches x 8 units = 64 threads)
            if (tid < NBH * NI) {
                int bb = tid >> 3, ii = tid & 7;
                int r3 = ii * 3;
                float ir  = gis[bb * NROWB + r3]     + bih_s[r3];
                float iz  = gis[bb * NROWB + r3 + 1] + bih_s[r3 + 1];
                float inn = gis[bb * NROWB + r3 + 2] + bih_s[r3 + 2];
                float hr  = ghs[bb * NROWB + r3]     + bhh_s[r3];
                float hz  = ghs[bb * NROWB + r3 + 1] + bhh_s[r3 + 1];
                float hn  = ghs[bb * NROWB + r3 + 2] + bhh_s[r3 + 2];
                float r = 1.f / (1.f + expf(-(ir + hr)));
                float z = 1.f / (1.f + expf(-(iz + hz)));
                float n = tanhf(inn + r * hn);
                float hold = hss[bb * HS_STR + i0 + ii];
                g_h[(b0 + sb + bb) * Hsz + i0 + ii] = (1.f - z) * n + z * hold;
            }
            bar_release(s, ++tgt[s]);               // publish h_new (syncthreads inside)

            // prefetch x[t+1], mask[t+1] for this stream (overlaps everything)
            for (int idx = tid; idx < NBH * Dsz; idx += THREADS) {
                int bb = idx / Dsz, k = idx - bb * Dsz;
                size_t o = ((size_t)(b0 + sb + bb) * Ssz + (t + 1)) * Dsz + k;
                xss[bb * XS_STR + k] = x[o];
                xss[bb * XS_STR + Dsz + k] = mask[o];
            }
        }
    }
}

static const int SMEM_BYTES =
    (NROWB * XS_STR + 31 * HS_STR + 2 * NBH * XS_STR + 2 * NBH * HS_STR +
     4 * NBH * NROWB + 2 * NROWB + 8) * (int)sizeof(float);

extern "C" void kernel_launch(void* const* d_in, const int* in_sizes, int n_in,
                              void* d_out, int out_size) {
    const float* x    = (const float*)d_in[0];
    const float* mask = (const float*)d_in[1];
    const float* Wih  = (const float*)d_in[2];
    const float* Whh  = (const float*)d_in[3];
    const float* bih  = (const float*)d_in[4];
    const float* bhh  = (const float*)d_in[5];
    const float* Wro  = (const float*)d_in[6];
    const float* bro  = (const float*)d_in[7];
    float* out = (float*)d_out;

    cudaFuncSetAttribute(rnn_imputer_kernel,
                         cudaFuncAttributeMaxDynamicSharedMemorySize, SMEM_BYTES);
    rnn_imputer_kernel<<<GRID, THREADS, SMEM_BYTES>>>(x, mask, Wih, Whh, bih, bhh,
                                                      Wro, bro, out);
}